// round 4
// baseline (speedup 1.0000x reference)
#include <cuda_runtime.h>
#include <stdint.h>

#define N_NODES 50000
#define N_EDGES 50000
#define N_PAIRS 800000
#define IN_CH   512
#define HID0    256
#define HID1    128
#define N_TGT   32

// ---------------- scratch (static device globals; no cudaMalloc allowed) ----
__device__ float g_h   [(size_t)N_NODES * HID0];   // GEMM output
__device__ float g_fte [(size_t)N_EDGES * HID0];   // edge features
__device__ float g_hout[(size_t)N_NODES * HID0];   // hyconv output / next input
__device__ float g_invDe[N_EDGES], g_invDn[N_NODES];
__device__ int   g_cnt_e[N_EDGES], g_cnt_n[N_NODES];
__device__ int   g_off_e[N_EDGES], g_off_n[N_NODES];
__device__ int   g_cur_e[N_EDGES], g_cur_n[N_NODES];
__device__ int   g_adj_e[N_PAIRS];   // node ids grouped by edge
__device__ int   g_adj_n[N_PAIRS];   // edge ids grouped by node
__device__ unsigned char g_mask[(size_t)N_NODES * HID0];
__device__ float g_pool[HID1];

// ---------------- threefry2x32 (exact JAX semantics) ------------------------
__host__ __device__ __forceinline__ uint32_t rotl32(uint32_t x, int d) {
    return (x << d) | (x >> (32 - d));
}
__host__ __device__ __forceinline__ void threefry2x32(
    uint32_t k0, uint32_t k1, uint32_t x0, uint32_t x1,
    uint32_t& o0, uint32_t& o1)
{
    uint32_t k2 = k0 ^ k1 ^ 0x1BD11BDAu;
    x0 += k0; x1 += k1;
    x0 += x1; x1 = rotl32(x1,13); x1 ^= x0;
    x0 += x1; x1 = rotl32(x1,15); x1 ^= x0;
    x0 += x1; x1 = rotl32(x1,26); x1 ^= x0;
    x0 += x1; x1 = rotl32(x1, 6); x1 ^= x0;
    x0 += k1; x1 += k2 + 1u;
    x0 += x1; x1 = rotl32(x1,17); x1 ^= x0;
    x0 += x1; x1 = rotl32(x1,29); x1 ^= x0;
    x0 += x1; x1 = rotl32(x1,16); x1 ^= x0;
    x0 += x1; x1 = rotl32(x1,24); x1 ^= x0;
    x0 += k2; x1 += k0 + 2u;
    x0 += x1; x1 = rotl32(x1,13); x1 ^= x0;
    x0 += x1; x1 = rotl32(x1,15); x1 ^= x0;
    x0 += x1; x1 = rotl32(x1,26); x1 ^= x0;
    x0 += x1; x1 = rotl32(x1, 6); x1 ^= x0;
    x0 += k0; x1 += k1 + 3u;
    x0 += x1; x1 = rotl32(x1,17); x1 ^= x0;
    x0 += x1; x1 = rotl32(x1,29); x1 ^= x0;
    x0 += x1; x1 = rotl32(x1,16); x1 ^= x0;
    x0 += x1; x1 = rotl32(x1,24); x1 ^= x0;
    x0 += k1; x1 += k2 + 4u;
    x0 += x1; x1 = rotl32(x1,13); x1 ^= x0;
    x0 += x1; x1 = rotl32(x1,15); x1 ^= x0;
    x0 += x1; x1 = rotl32(x1,26); x1 ^= x0;
    x0 += x1; x1 = rotl32(x1, 6); x1 ^= x0;
    x0 += k2; x1 += k0 + 5u;
    o0 = x0; o1 = x1;
}

// ---------------- small setup kernels ---------------------------------------
__global__ void k_zero() {
    int i = blockIdx.x * blockDim.x + threadIdx.x;
    if (i < N_EDGES) g_cnt_e[i] = 0;
    if (i < N_NODES) g_cnt_n[i] = 0;
    if (i < HID1)    g_pool[i]  = 0.f;
}

__global__ void k_degree(const int* __restrict__ H) {
    int p = blockIdx.x * blockDim.x + threadIdx.x;
    if (p < N_PAIRS) {
        atomicAdd(&g_cnt_n[H[p]], 1);
        atomicAdd(&g_cnt_e[H[N_PAIRS + p]], 1);
    }
}

__global__ void k_invd() {
    int i = blockIdx.x * blockDim.x + threadIdx.x;
    if (i < N_EDGES) g_invDe[i] = 1.0f / fmaxf((float)g_cnt_e[i], 1.0f);
    if (i < N_NODES) g_invDn[i] = 1.0f / fmaxf((float)g_cnt_n[i], 1.0f);
}

// exclusive scan of 50000 counts; block 0 -> edges, block 1 -> nodes
__global__ void k_scan2() {
    const int* cnt = blockIdx.x ? g_cnt_n : g_cnt_e;
    int* off       = blockIdx.x ? g_off_n : g_off_e;
    int* cur       = blockIdx.x ? g_cur_n : g_cur_e;
    __shared__ int wsum[32];
    __shared__ int s_carry;
    if (threadIdx.x == 0) s_carry = 0;
    __syncthreads();
    int lane = threadIdx.x & 31, w = threadIdx.x >> 5;
    for (int base = 0; base < N_EDGES; base += 1024) {
        int i = base + threadIdx.x;
        int v = (i < N_EDGES) ? cnt[i] : 0;
        int x = v;
        #pragma unroll
        for (int o = 1; o < 32; o <<= 1) {
            int y = __shfl_up_sync(0xffffffffu, x, o);
            if (lane >= o) x += y;
        }
        if (lane == 31) wsum[w] = x;
        __syncthreads();
        if (w == 0) {
            int s = wsum[lane];
            #pragma unroll
            for (int o = 1; o < 32; o <<= 1) {
                int y = __shfl_up_sync(0xffffffffu, s, o);
                if (lane >= o) s += y;
            }
            wsum[lane] = s;
        }
        __syncthreads();
        int woff = (w > 0) ? wsum[w - 1] : 0;
        int incl = x + woff + s_carry;
        if (i < N_EDGES) { off[i] = incl - v; cur[i] = incl - v; }
        __syncthreads();
        if (threadIdx.x == 1023) s_carry = incl;
        __syncthreads();
    }
}

__global__ void k_fill(const int* __restrict__ H) {
    int p = blockIdx.x * blockDim.x + threadIdx.x;
    if (p < N_PAIRS) {
        int n = H[p], e = H[N_PAIRS + p];
        g_adj_e[atomicAdd(&g_cur_e[e], 1)] = n;
        g_adj_n[atomicAdd(&g_cur_n[n], 1)] = e;
    }
}

// ---------------- SGEMM: C[M,N] = A[M,K] @ B[K,N] (128x128x8, 8x8/thread) ---
__global__ void k_gemm(const float* __restrict__ A, const float* __restrict__ B,
                       float* __restrict__ C, int M, int N, int K) {
    __shared__ float As[8][128];
    __shared__ float Bs[8][132];
    int tid = threadIdx.x;
    int bm = blockIdx.x * 128;
    int bn = blockIdx.y * 128;
    int tx = tid & 15, ty = tid >> 4;
    int arow = tid >> 1, acol = (tid & 1) << 2;
    int brow = tid >> 5, bcol = (tid & 31) << 2;
    float acc[8][8];
    #pragma unroll
    for (int i = 0; i < 8; i++)
        #pragma unroll
        for (int j = 0; j < 8; j++) acc[i][j] = 0.f;

    for (int k0 = 0; k0 < K; k0 += 8) {
        float4 av;
        if (bm + arow < M) av = *(const float4*)(A + (size_t)(bm + arow) * K + k0 + acol);
        else av = make_float4(0.f, 0.f, 0.f, 0.f);
        As[acol + 0][arow] = av.x; As[acol + 1][arow] = av.y;
        As[acol + 2][arow] = av.z; As[acol + 3][arow] = av.w;
        float4 bv = *(const float4*)(B + (size_t)(k0 + brow) * N + bn + bcol);
        Bs[brow][bcol + 0] = bv.x; Bs[brow][bcol + 1] = bv.y;
        Bs[brow][bcol + 2] = bv.z; Bs[brow][bcol + 3] = bv.w;
        __syncthreads();
        #pragma unroll
        for (int kk = 0; kk < 8; kk++) {
            float ra[8], rb[8];
            #pragma unroll
            for (int i = 0; i < 8; i++) ra[i] = As[kk][ty * 8 + i];
            #pragma unroll
            for (int j = 0; j < 8; j++) rb[j] = Bs[kk][tx * 8 + j];
            #pragma unroll
            for (int i = 0; i < 8; i++)
                #pragma unroll
                for (int j = 0; j < 8; j++) acc[i][j] += ra[i] * rb[j];
        }
        __syncthreads();
    }
    #pragma unroll
    for (int i = 0; i < 8; i++) {
        int row = bm + ty * 8 + i;
        if (row < M) {
            float4* cp = (float4*)(C + (size_t)row * N + bn + tx * 8);
            cp[0] = make_float4(acc[i][0], acc[i][1], acc[i][2], acc[i][3]);
            cp[1] = make_float4(acc[i][4], acc[i][5], acc[i][6], acc[i][7]);
        }
    }
}

// ---------------- sparse gathers (CSR, no atomics) ---------------------------
template<int C>
__global__ void k_edge_gather(const float* __restrict__ h, float* __restrict__ fte) {
    int e = blockIdx.x;
    int c = threadIdx.x;
    int s = g_off_e[e], m = g_cnt_e[e];
    const int* adj = g_adj_e + s;
    float acc = 0.f;
    int j = 0;
    for (; j + 4 <= m; j += 4) {
        int n0 = adj[j], n1 = adj[j + 1], n2 = adj[j + 2], n3 = adj[j + 3];
        float a = h[(size_t)n0 * C + c];
        float b = h[(size_t)n1 * C + c];
        float d = h[(size_t)n2 * C + c];
        float f = h[(size_t)n3 * C + c];
        acc += a + b + d + f;
    }
    for (; j < m; j++) acc += h[(size_t)adj[j] * C + c];
    fte[(size_t)e * C + c] = acc * g_invDe[e];
}

template<int C>
__global__ void k_node_apply(const float* __restrict__ fte,
                             const float* __restrict__ bias,
                             float* __restrict__ out) {
    int n = blockIdx.x;
    int c = threadIdx.x;
    int s = g_off_n[n], m = g_cnt_n[n];
    const int* adj = g_adj_n + s;
    float acc = 0.f;
    int j = 0;
    for (; j + 4 <= m; j += 4) {
        int e0 = adj[j], e1 = adj[j + 1], e2 = adj[j + 2], e3 = adj[j + 3];
        float a = fte[(size_t)e0 * C + c];
        float b = fte[(size_t)e1 * C + c];
        float d = fte[(size_t)e2 * C + c];
        float f = fte[(size_t)e3 * C + c];
        acc += a + b + d + f;
    }
    for (; j < m; j++) acc += fte[(size_t)adj[j] * C + c];
    float v = acc * g_invDn[n] + bias[c];
    v = (v >= 0.f) ? v : 0.01f * v;          // leaky relu
    size_t idx = (size_t)n * C + c;
    v = g_mask[idx] ? v * 2.0f : 0.0f;        // dropout p=0.5 -> /0.5
    out[idx] = v;
}

// ---------------- dropout mask (JAX partitionable-threefry bernoulli) --------
// jax_threefry_partitionable=True (default in modern JAX), bit_width=32:
//   counts1, counts2 = hi/lo 32 bits of the 64-bit row-major iota
//   bits1, bits2 = threefry2x32(key, counts1, counts2)
//   word(i) = bits1 ^ bits2            (then >> (32-32) == no shift)
//   keep  <=>  uniform(word) < 0.5  <=>  top bit of word == 0.
__global__ void k_mask(uint32_t k0, uint32_t k1, int n) {
    int i = blockIdx.x * blockDim.x + threadIdx.x;
    if (i < n) {
        uint32_t o0, o1;
        threefry2x32(k0, k1, 0u, (uint32_t)i, o0, o1);
        g_mask[i] = ((o0 ^ o1) >> 31) == 0u;
    }
}

// ---------------- dropmax (top-12 zeroed, JAX tie-break) + pooled sum -------
__global__ void k_dropmax(const float* __restrict__ h, float* __restrict__ feats,
                          float* __restrict__ pool) {
    __shared__ float s_pool[HID1];
    int t = threadIdx.x;
    if (t < HID1) s_pool[t] = 0.f;
    __syncthreads();
    int warp = t >> 5, lane = t & 31;
    int row = blockIdx.x * (blockDim.x >> 5) + warp;
    if (row < N_NODES) {
        float4 v4 = ((const float4*)(h + (size_t)row * HID1))[lane];
        float v[4] = {v4.x, v4.y, v4.z, v4.w};
        unsigned long long key[4];
        bool rem[4] = {false, false, false, false};
        #pragma unroll
        for (int j = 0; j < 4; j++) {
            uint32_t b = __float_as_uint(v[j]);
            uint32_t ord = (b & 0x80000000u) ? ~b : (b | 0x80000000u);
            key[j] = ((unsigned long long)ord << 32) |
                     (unsigned long long)(uint32_t)(127 - (lane * 4 + j));
        }
        for (int it = 0; it < 12; it++) {
            unsigned long long best = 0ull;
            #pragma unroll
            for (int j = 0; j < 4; j++) if (!rem[j] && key[j] > best) best = key[j];
            #pragma unroll
            for (int o = 16; o > 0; o >>= 1) {
                unsigned long long other = __shfl_xor_sync(0xffffffffu, best, o);
                if (other > best) best = other;
            }
            #pragma unroll
            for (int j = 0; j < 4; j++) if (key[j] == best) rem[j] = true;
        }
        #pragma unroll
        for (int j = 0; j < 4; j++) if (rem[j]) v[j] = 0.f;
        ((float4*)(feats + (size_t)row * HID1))[lane] =
            make_float4(v[0], v[1], v[2], v[3]);
        #pragma unroll
        for (int j = 0; j < 4; j++) atomicAdd(&s_pool[lane * 4 + j], v[j]);
    }
    __syncthreads();
    if (t < HID1) atomicAdd(&pool[t], s_pool[t]);
}

// ---------------- head: mean, fc, sigmoid ------------------------------------
__global__ void k_final(const float* __restrict__ Wfc, const float* __restrict__ bfc,
                        float* __restrict__ d_out) {
    __shared__ float p[HID1];
    int t = threadIdx.x;
    if (t < HID1) {
        float pv = g_pool[t] * (1.0f / (float)N_NODES);
        p[t] = pv;
        d_out[32 + (size_t)N_NODES * HID1 + t] = pv;   // feats_pool
    }
    __syncthreads();
    if (t < N_TGT) {
        float acc = bfc[t];
        #pragma unroll 8
        for (int c = 0; c < HID1; c++) acc += p[c] * Wfc[c * N_TGT + t];
        d_out[t] = 1.0f / (1.0f + expf(-acc));
    }
}

// ---------------- launch ------------------------------------------------------
extern "C" void kernel_launch(void* const* d_in, const int* in_sizes, int n_in,
                              void* d_out, int out_size) {
    const float* x   = (const float*)d_in[0];
    const int*   H   = (const int*)  d_in[1];
    const float* W0  = (const float*)d_in[2];
    const float* b0  = (const float*)d_in[3];
    const float* W1  = (const float*)d_in[4];
    const float* b1  = (const float*)d_in[5];
    const float* Wfc = (const float*)d_in[6];
    const float* bfc = (const float*)d_in[7];
    float* out = (float*)d_out;

    float *p_h, *p_fte, *p_hout, *p_pool;
    cudaGetSymbolAddress((void**)&p_h,    g_h);
    cudaGetSymbolAddress((void**)&p_fte,  g_fte);
    cudaGetSymbolAddress((void**)&p_hout, g_hout);
    cudaGetSymbolAddress((void**)&p_pool, g_pool);

    // JAX keys: base key(42) = (0,42); fold_in(key, i) = threefry(key, (0, i))
    uint32_t l0k0, l0k1, l1k0, l1k1;
    threefry2x32(0u, 42u, 0u, 0u, l0k0, l0k1);
    threefry2x32(0u, 42u, 0u, 1u, l1k0, l1k1);

    // degrees + CSR adjacency (built every launch, deterministic work)
    k_zero  <<<196, 256>>>();
    k_degree<<<(N_PAIRS + 255) / 256, 256>>>(H);
    k_invd  <<<196, 256>>>();
    k_scan2 <<<2, 1024>>>();
    k_fill  <<<(N_PAIRS + 255) / 256, 256>>>(H);

    // ----- layer 0 -----
    k_gemm<<<dim3((N_NODES + 127) / 128, HID0 / 128), 256>>>(x, W0, p_h,
                                                             N_NODES, HID0, IN_CH);
    k_edge_gather<HID0><<<N_EDGES, HID0>>>(p_h, p_fte);
    k_mask<<<(N_NODES * HID0 + 1023) / 1024, 1024>>>(l0k0, l0k1, N_NODES * HID0);
    k_node_apply<HID0><<<N_NODES, HID0>>>(p_fte, b0, p_hout);

    // ----- layer 1 -----
    k_gemm<<<dim3((N_NODES + 127) / 128, HID1 / 128), 256>>>(p_hout, W1, p_h,
                                                             N_NODES, HID1, HID0);
    k_edge_gather<HID1><<<N_EDGES, HID1>>>(p_h, p_fte);
    k_mask<<<(N_NODES * HID1 + 1023) / 1024, 1024>>>(l1k0, l1k1, N_NODES * HID1);
    k_node_apply<HID1><<<N_NODES, HID1>>>(p_fte, b1, p_hout);

    // ----- dropmax + pool + head -----
    k_dropmax<<<(N_NODES + 7) / 8, 256>>>(p_hout, out + 32, p_pool);
    k_final<<<1, 128>>>(Wfc, bfc, out);
}

// round 5
// speedup vs baseline: 1.1419x; 1.1419x over previous
#include <cuda_runtime.h>
#include <stdint.h>

#define N_NODES 50000
#define N_EDGES 50000
#define N_PAIRS 800000
#define IN_CH   512
#define HID0    256
#define HID1    128
#define N_TGT   32

// ---------------- scratch (static device globals; no cudaMalloc allowed) ----
__device__ float g_h   [(size_t)N_NODES * HID0];   // GEMM output
__device__ float g_fte [(size_t)N_EDGES * HID0];   // edge features
__device__ float g_hout[(size_t)N_NODES * HID0];   // hyconv output / next input
__device__ float g_invDe[N_EDGES], g_invDn[N_NODES];
__device__ int   g_cnt_e[N_EDGES], g_cnt_n[N_NODES];
__device__ int   g_off_e[N_EDGES], g_off_n[N_NODES];
__device__ int   g_cur_e[N_EDGES], g_cur_n[N_NODES];
__device__ int   g_adj_e[N_PAIRS];   // node ids grouped by edge
__device__ int   g_adj_n[N_PAIRS];   // edge ids grouped by node
__device__ int   g_bsum[2][64];      // per-block scan partials
__device__ float g_pool[HID1];

// ---------------- threefry2x32 (exact JAX semantics) ------------------------
__host__ __device__ __forceinline__ uint32_t rotl32(uint32_t x, int d) {
    return (x << d) | (x >> (32 - d));
}
__host__ __device__ __forceinline__ void threefry2x32(
    uint32_t k0, uint32_t k1, uint32_t x0, uint32_t x1,
    uint32_t& o0, uint32_t& o1)
{
    uint32_t k2 = k0 ^ k1 ^ 0x1BD11BDAu;
    x0 += k0; x1 += k1;
    x0 += x1; x1 = rotl32(x1,13); x1 ^= x0;
    x0 += x1; x1 = rotl32(x1,15); x1 ^= x0;
    x0 += x1; x1 = rotl32(x1,26); x1 ^= x0;
    x0 += x1; x1 = rotl32(x1, 6); x1 ^= x0;
    x0 += k1; x1 += k2 + 1u;
    x0 += x1; x1 = rotl32(x1,17); x1 ^= x0;
    x0 += x1; x1 = rotl32(x1,29); x1 ^= x0;
    x0 += x1; x1 = rotl32(x1,16); x1 ^= x0;
    x0 += x1; x1 = rotl32(x1,24); x1 ^= x0;
    x0 += k2; x1 += k0 + 2u;
    x0 += x1; x1 = rotl32(x1,13); x1 ^= x0;
    x0 += x1; x1 = rotl32(x1,15); x1 ^= x0;
    x0 += x1; x1 = rotl32(x1,26); x1 ^= x0;
    x0 += x1; x1 = rotl32(x1, 6); x1 ^= x0;
    x0 += k0; x1 += k1 + 3u;
    x0 += x1; x1 = rotl32(x1,17); x1 ^= x0;
    x0 += x1; x1 = rotl32(x1,29); x1 ^= x0;
    x0 += x1; x1 = rotl32(x1,16); x1 ^= x0;
    x0 += x1; x1 = rotl32(x1,24); x1 ^= x0;
    x0 += k1; x1 += k2 + 4u;
    x0 += x1; x1 = rotl32(x1,13); x1 ^= x0;
    x0 += x1; x1 = rotl32(x1,15); x1 ^= x0;
    x0 += x1; x1 = rotl32(x1,26); x1 ^= x0;
    x0 += x1; x1 = rotl32(x1, 6); x1 ^= x0;
    x0 += k2; x1 += k0 + 5u;
    o0 = x0; o1 = x1;
}

// ---------------- small setup kernels ---------------------------------------
__global__ void k_zero() {
    int i = blockIdx.x * blockDim.x + threadIdx.x;
    if (i < N_EDGES) g_cnt_e[i] = 0;
    if (i < N_NODES) g_cnt_n[i] = 0;
    if (i < HID1)    g_pool[i]  = 0.f;
}

__global__ void k_degree(const int* __restrict__ H) {
    int p = blockIdx.x * blockDim.x + threadIdx.x;
    if (p < N_PAIRS) {
        atomicAdd(&g_cnt_n[H[p]], 1);
        atomicAdd(&g_cnt_e[H[N_PAIRS + p]], 1);
    }
}

// ---------------- 3-phase parallel exclusive scan ----------------------------
// phase 1: per-block (1024 items) local exclusive scan, block sums to g_bsum
__global__ void k_scan_part() {
    int arr = blockIdx.y;
    const int* cnt = arr ? g_cnt_n : g_cnt_e;
    int* off       = arr ? g_off_n : g_off_e;
    __shared__ int wsum[32];
    int i = blockIdx.x * 1024 + threadIdx.x;
    int lane = threadIdx.x & 31, w = threadIdx.x >> 5;
    int v = (i < N_EDGES) ? cnt[i] : 0;
    int x = v;
    #pragma unroll
    for (int o = 1; o < 32; o <<= 1) {
        int y = __shfl_up_sync(0xffffffffu, x, o);
        if (lane >= o) x += y;
    }
    if (lane == 31) wsum[w] = x;
    __syncthreads();
    if (w == 0) {
        int s = wsum[lane];
        #pragma unroll
        for (int o = 1; o < 32; o <<= 1) {
            int y = __shfl_up_sync(0xffffffffu, s, o);
            if (lane >= o) s += y;
        }
        wsum[lane] = s;
    }
    __syncthreads();
    int incl = x + ((w > 0) ? wsum[w - 1] : 0);
    if (i < N_EDGES) off[i] = incl - v;          // local exclusive
    if (threadIdx.x == 1023) g_bsum[arr][blockIdx.x] = incl;
}

// phase 2: scan the 49 block sums (inclusive), one block per array
__global__ void k_scan_top() {
    int arr = blockIdx.x;
    __shared__ int s[64];
    int t = threadIdx.x;
    s[t] = (t < 49) ? g_bsum[arr][t] : 0;
    __syncthreads();
    #pragma unroll
    for (int o = 1; o < 64; o <<= 1) {
        int val = (t >= o) ? s[t - o] : 0;
        __syncthreads();
        s[t] += val;
        __syncthreads();
    }
    if (t < 49) g_bsum[arr][t] = s[t];
}

// phase 3: add block offsets; also finalize cur[] and invD[] (fused k_invd)
__global__ void k_scan_add() {
    int arr = blockIdx.y;
    int i = blockIdx.x * 1024 + threadIdx.x;
    if (i >= N_EDGES) return;
    int add = blockIdx.x ? g_bsum[arr][blockIdx.x - 1] : 0;
    if (arr == 0) {
        int o = g_off_e[i] + add;
        g_off_e[i] = o; g_cur_e[i] = o;
        g_invDe[i] = 1.0f / fmaxf((float)g_cnt_e[i], 1.0f);
    } else {
        int o = g_off_n[i] + add;
        g_off_n[i] = o; g_cur_n[i] = o;
        g_invDn[i] = 1.0f / fmaxf((float)g_cnt_n[i], 1.0f);
    }
}

__global__ void k_fill(const int* __restrict__ H) {
    int p = blockIdx.x * blockDim.x + threadIdx.x;
    if (p < N_PAIRS) {
        int n = H[p], e = H[N_PAIRS + p];
        g_adj_e[atomicAdd(&g_cur_e[e], 1)] = n;
        g_adj_n[atomicAdd(&g_cur_n[n], 1)] = e;
    }
}

// ---------------- SGEMM with packed fp32x2 FMA (FFMA2) ----------------------
// C[M,N] = A[M,K] @ B[K,N]; 128x128x8 tile, 8x8 per thread as 8x(4 f32x2 pairs).
// fma.rn.f32x2 = two independent fp32 FMAs per issue slot (bit-identical math,
// 2x the FFMA issue throughput on sm_103a).
#define FMA2(d, a, b) asm("fma.rn.f32x2 %0, %1, %2, %0;" : "+l"(d) : "l"(a), "l"(b))

__global__ void k_gemm(const float* __restrict__ A, const float* __restrict__ B,
                       float* __restrict__ C, int M, int N, int K) {
    __shared__ float As[8][128];
    __shared__ float Bs[8][132];
    int tid = threadIdx.x;
    int bm = blockIdx.x * 128;
    int bn = blockIdx.y * 128;
    int tx = tid & 15, ty = tid >> 4;
    int arow = tid >> 1, acol = (tid & 1) << 2;
    int brow = tid >> 5, bcol = (tid & 31) << 2;
    unsigned long long acc[8][4];
    #pragma unroll
    for (int i = 0; i < 8; i++)
        #pragma unroll
        for (int j = 0; j < 4; j++) acc[i][j] = 0ull;

    for (int k0 = 0; k0 < K; k0 += 8) {
        float4 av;
        if (bm + arow < M) av = *(const float4*)(A + (size_t)(bm + arow) * K + k0 + acol);
        else av = make_float4(0.f, 0.f, 0.f, 0.f);
        As[acol + 0][arow] = av.x; As[acol + 1][arow] = av.y;
        As[acol + 2][arow] = av.z; As[acol + 3][arow] = av.w;
        float4 bv = *(const float4*)(B + (size_t)(k0 + brow) * N + bn + bcol);
        Bs[brow][bcol + 0] = bv.x; Bs[brow][bcol + 1] = bv.y;
        Bs[brow][bcol + 2] = bv.z; Bs[brow][bcol + 3] = bv.w;
        __syncthreads();
        #pragma unroll
        for (int kk = 0; kk < 8; kk++) {
            float4 a03 = *(const float4*)&As[kk][ty * 8];
            float4 a47 = *(const float4*)&As[kk][ty * 8 + 4];
            ulonglong2 b01 = *(const ulonglong2*)&Bs[kk][tx * 8];      // cols 0-3 as 2 pairs
            ulonglong2 b23 = *(const ulonglong2*)&Bs[kk][tx * 8 + 4];  // cols 4-7 as 2 pairs
            float avr[8] = {a03.x, a03.y, a03.z, a03.w, a47.x, a47.y, a47.z, a47.w};
            #pragma unroll
            for (int i = 0; i < 8; i++) {
                unsigned long long a2;
                asm("mov.b64 %0, {%1, %1};" : "=l"(a2) : "f"(avr[i]));
                FMA2(acc[i][0], a2, b01.x);
                FMA2(acc[i][1], a2, b01.y);
                FMA2(acc[i][2], a2, b23.x);
                FMA2(acc[i][3], a2, b23.y);
            }
        }
        __syncthreads();
    }
    #pragma unroll
    for (int i = 0; i < 8; i++) {
        int row = bm + ty * 8 + i;
        if (row < M) {
            float2 p0 = *(float2*)&acc[i][0];
            float2 p1 = *(float2*)&acc[i][1];
            float2 p2 = *(float2*)&acc[i][2];
            float2 p3 = *(float2*)&acc[i][3];
            float4* cp = (float4*)(C + (size_t)row * N + bn + tx * 8);
            cp[0] = make_float4(p0.x, p0.y, p1.x, p1.y);
            cp[1] = make_float4(p2.x, p2.y, p3.x, p3.y);
        }
    }
}

// ---------------- sparse gathers (CSR, no atomics) ---------------------------
template<int C>
__global__ void k_edge_gather(const float* __restrict__ h, float* __restrict__ fte) {
    int e = blockIdx.x;
    int c = threadIdx.x;
    int s = g_off_e[e], m = g_cnt_e[e];
    const int* adj = g_adj_e + s;
    float acc = 0.f;
    int j = 0;
    for (; j + 4 <= m; j += 4) {
        int n0 = adj[j], n1 = adj[j + 1], n2 = adj[j + 2], n3 = adj[j + 3];
        float a = h[(size_t)n0 * C + c];
        float b = h[(size_t)n1 * C + c];
        float d = h[(size_t)n2 * C + c];
        float f = h[(size_t)n3 * C + c];
        acc += a + b + d + f;
    }
    for (; j < m; j++) acc += h[(size_t)adj[j] * C + c];
    fte[(size_t)e * C + c] = acc * g_invDe[e];
}

// node aggregation + bias + leaky relu + fused JAX-threefry dropout
template<int C>
__global__ void k_node_apply(const float* __restrict__ fte,
                             const float* __restrict__ bias,
                             float* __restrict__ out,
                             uint32_t dk0, uint32_t dk1) {
    int n = blockIdx.x;
    int c = threadIdx.x;
    int s = g_off_n[n], m = g_cnt_n[n];
    const int* adj = g_adj_n + s;
    float acc = 0.f;
    int j = 0;
    for (; j + 4 <= m; j += 4) {
        int e0 = adj[j], e1 = adj[j + 1], e2 = adj[j + 2], e3 = adj[j + 3];
        float a = fte[(size_t)e0 * C + c];
        float b = fte[(size_t)e1 * C + c];
        float d = fte[(size_t)e2 * C + c];
        float f = fte[(size_t)e3 * C + c];
        acc += a + b + d + f;
    }
    for (; j < m; j++) acc += fte[(size_t)adj[j] * C + c];
    float v = acc * g_invDn[n] + bias[c];
    v = (v >= 0.f) ? v : 0.01f * v;          // leaky relu
    uint32_t idx = (uint32_t)n * C + c;      // row-major iota, < 2^32
    // JAX partitionable threefry, 32-bit: word = o0 ^ o1 of threefry(key, 0, i)
    uint32_t o0, o1;
    threefry2x32(dk0, dk1, 0u, idx, o0, o1);
    v = (((o0 ^ o1) >> 31) == 0u) ? v * 2.0f : 0.0f;   // keep <=> u < 0.5
    out[(size_t)n * C + c] = v;
}

// ---------------- dropmax (top-12 zeroed, JAX tie-break) + pooled sum -------
__global__ void k_dropmax(const float* __restrict__ h, float* __restrict__ feats,
                          float* __restrict__ pool) {
    __shared__ float s_pool[HID1];
    int t = threadIdx.x;
    if (t < HID1) s_pool[t] = 0.f;
    __syncthreads();
    int warp = t >> 5, lane = t & 31;
    int row = blockIdx.x * (blockDim.x >> 5) + warp;
    if (row < N_NODES) {
        float4 v4 = ((const float4*)(h + (size_t)row * HID1))[lane];
        float v[4] = {v4.x, v4.y, v4.z, v4.w};
        unsigned long long key[4];
        bool rem[4] = {false, false, false, false};
        #pragma unroll
        for (int j = 0; j < 4; j++) {
            uint32_t b = __float_as_uint(v[j]);
            uint32_t ord = (b & 0x80000000u) ? ~b : (b | 0x80000000u);
            key[j] = ((unsigned long long)ord << 32) |
                     (unsigned long long)(uint32_t)(127 - (lane * 4 + j));
        }
        for (int it = 0; it < 12; it++) {
            unsigned long long best = 0ull;
            #pragma unroll
            for (int j = 0; j < 4; j++) if (!rem[j] && key[j] > best) best = key[j];
            #pragma unroll
            for (int o = 16; o > 0; o >>= 1) {
                unsigned long long other = __shfl_xor_sync(0xffffffffu, best, o);
                if (other > best) best = other;
            }
            #pragma unroll
            for (int j = 0; j < 4; j++) if (key[j] == best) rem[j] = true;
        }
        #pragma unroll
        for (int j = 0; j < 4; j++) if (rem[j]) v[j] = 0.f;
        ((float4*)(feats + (size_t)row * HID1))[lane] =
            make_float4(v[0], v[1], v[2], v[3]);
        #pragma unroll
        for (int j = 0; j < 4; j++) atomicAdd(&s_pool[lane * 4 + j], v[j]);
    }
    __syncthreads();
    if (t < HID1) atomicAdd(&pool[t], s_pool[t]);
}

// ---------------- head: mean, fc, sigmoid ------------------------------------
__global__ void k_final(const float* __restrict__ Wfc, const float* __restrict__ bfc,
                        float* __restrict__ d_out) {
    __shared__ float p[HID1];
    int t = threadIdx.x;
    if (t < HID1) {
        float pv = g_pool[t] * (1.0f / (float)N_NODES);
        p[t] = pv;
        d_out[32 + (size_t)N_NODES * HID1 + t] = pv;   // feats_pool
    }
    __syncthreads();
    if (t < N_TGT) {
        float acc = bfc[t];
        #pragma unroll 8
        for (int c = 0; c < HID1; c++) acc += p[c] * Wfc[c * N_TGT + t];
        d_out[t] = 1.0f / (1.0f + expf(-acc));
    }
}

// ---------------- launch ------------------------------------------------------
extern "C" void kernel_launch(void* const* d_in, const int* in_sizes, int n_in,
                              void* d_out, int out_size) {
    const float* x   = (const float*)d_in[0];
    const int*   H   = (const int*)  d_in[1];
    const float* W0  = (const float*)d_in[2];
    const float* b0  = (const float*)d_in[3];
    const float* W1  = (const float*)d_in[4];
    const float* b1  = (const float*)d_in[5];
    const float* Wfc = (const float*)d_in[6];
    const float* bfc = (const float*)d_in[7];
    float* out = (float*)d_out;

    float *p_h, *p_fte, *p_hout, *p_pool;
    cudaGetSymbolAddress((void**)&p_h,    g_h);
    cudaGetSymbolAddress((void**)&p_fte,  g_fte);
    cudaGetSymbolAddress((void**)&p_hout, g_hout);
    cudaGetSymbolAddress((void**)&p_pool, g_pool);

    // JAX keys: base key(42) = (0,42); fold_in(key, i) = threefry(key, (0, i))
    uint32_t l0k0, l0k1, l1k0, l1k1;
    threefry2x32(0u, 42u, 0u, 0u, l0k0, l0k1);
    threefry2x32(0u, 42u, 0u, 1u, l1k0, l1k1);

    const int NBLK = (N_EDGES + 1023) / 1024;   // 49

    // degrees + CSR adjacency (built every launch, deterministic work)
    k_zero     <<<196, 256>>>();
    k_degree   <<<(N_PAIRS + 255) / 256, 256>>>(H);
    k_scan_part<<<dim3(NBLK, 2), 1024>>>();
    k_scan_top <<<2, 64>>>();
    k_scan_add <<<dim3(NBLK, 2), 1024>>>();
    k_fill     <<<(N_PAIRS + 255) / 256, 256>>>(H);

    // ----- layer 0 -----
    k_gemm<<<dim3((N_NODES + 127) / 128, HID0 / 128), 256>>>(x, W0, p_h,
                                                             N_NODES, HID0, IN_CH);
    k_edge_gather<HID0><<<N_EDGES, HID0>>>(p_h, p_fte);
    k_node_apply<HID0><<<N_NODES, HID0>>>(p_fte, b0, p_hout, l0k0, l0k1);

    // ----- layer 1 -----
    k_gemm<<<dim3((N_NODES + 127) / 128, HID1 / 128), 256>>>(p_hout, W1, p_h,
                                                             N_NODES, HID1, HID0);
    k_edge_gather<HID1><<<N_EDGES, HID1>>>(p_h, p_fte);
    k_node_apply<HID1><<<N_NODES, HID1>>>(p_fte, b1, p_hout, l1k0, l1k1);

    // ----- dropmax + pool + head -----
    k_dropmax<<<(N_NODES + 7) / 8, 256>>>(p_hout, out + 32, p_pool);
    k_final<<<1, 128>>>(Wfc, bfc, out);
}